// round 16
// baseline (speedup 1.0000x reference)
#include <cuda_runtime.h>
#include <cstdint>
#include <cstdio>

#define T_STEPS 1000
#define BATCH   16
#define IFEAT   440
#define HID     1024
#define PROJ    512
#define NCTA    128
#define GFOUR   4096   // 4*HID

// ---------------- scratch ----------------
__device__ float    g_G[(size_t)T_STEPS * BATCH * GFOUR]; // [t*16+b][g*1024+h]
__device__ float    g_U[(size_t)4 * HID * HID];           // [g][h][hh]
__device__ unsigned g_flags[NCTA];                        // packed per-CTA step flags

// ---------------- f32x2 helpers ----------------
__device__ __forceinline__ unsigned long long pk2(float x, float y) {
    unsigned long long r;
    asm("mov.b64 %0, {%1, %2};" : "=l"(r) : "f"(x), "f"(y));
    return r;
}
__device__ __forceinline__ void upk2(unsigned long long v, float& x, float& y) {
    asm("mov.b64 {%0, %1}, %2;" : "=f"(x), "=f"(y) : "l"(v));
}
__device__ __forceinline__ unsigned long long ffma2(unsigned long long a,
                                                    unsigned long long b,
                                                    unsigned long long c) {
    unsigned long long d;
    asm("fma.rn.f32x2 %0, %1, %2, %3;" : "=l"(d) : "l"(a), "l"(b), "l"(c));
    return d;
}

// fast sigmoid / tanh (MUFU-based)
__device__ __forceinline__ float fsig(float x) {
    return __fdividef(1.0f, 1.0f + __expf(-x));
}
__device__ __forceinline__ float ftanh(float x) {
    return 1.0f - __fdividef(2.0f, __expf(2.0f * x) + 1.0f);
}

// ---------------- init ----------------
__global__ void k_init() {
    if (threadIdx.x < NCTA) g_flags[threadIdx.x] = 0u;
}

// =====================================================================
// Input GEMM: G[m][g*1024+n] = x[m][:] . w_g[n][:] + b_g[n]
// =====================================================================
__global__ __launch_bounds__(256) void k_gemm_in(
    const float* __restrict__ x,
    const float* __restrict__ wf, const float* __restrict__ bf,
    const float* __restrict__ wi, const float* __restrict__ bi,
    const float* __restrict__ wo, const float* __restrict__ bo,
    const float* __restrict__ wc, const float* __restrict__ bc)
{
    __shared__ float As[8][132];
    __shared__ float Bs[8][132];

    const int bx = blockIdx.x;            // 0..31 (n tile)
    const int by = blockIdx.y;            // 0..124 (m tile)
    const int g  = bx >> 3;
    const int nloc0 = (bx & 7) * 128;
    const float* wp = (g == 0) ? wf : (g == 1) ? wi : (g == 2) ? wo : wc;
    const float* bp = (g == 0) ? bf : (g == 1) ? bi : (g == 2) ? bo : bc;

    const int tid  = threadIdx.x;
    const int lrow = tid >> 1;
    const int kq   = (tid & 1) * 4;
    const int tx   = tid & 15;
    const int ty   = tid >> 4;

    unsigned long long acc[8][4];
#pragma unroll
    for (int i = 0; i < 8; i++)
#pragma unroll
        for (int j = 0; j < 4; j++) acc[i][j] = 0ULL;

    const int m0 = by * 128;
    const float* Aptr = x  + (size_t)(m0 + lrow)    * IFEAT + kq;
    const float* Bptr = wp + (size_t)(nloc0 + lrow) * IFEAT + kq;

    for (int k0 = 0; k0 < IFEAT; k0 += 8) {
        float4 av = *(const float4*)(Aptr + k0);
        float4 bv = *(const float4*)(Bptr + k0);
        As[kq + 0][lrow] = av.x; As[kq + 1][lrow] = av.y;
        As[kq + 2][lrow] = av.z; As[kq + 3][lrow] = av.w;
        Bs[kq + 0][lrow] = bv.x; Bs[kq + 1][lrow] = bv.y;
        Bs[kq + 2][lrow] = bv.z; Bs[kq + 3][lrow] = bv.w;
        __syncthreads();
#pragma unroll
        for (int kk = 0; kk < 8; kk++) {
            float4 a0 = *(const float4*)&As[kk][ty * 8];
            float4 a1 = *(const float4*)&As[kk][ty * 8 + 4];
            float4 b0 = *(const float4*)&Bs[kk][tx * 8];
            float4 b1 = *(const float4*)&Bs[kk][tx * 8 + 4];
            unsigned long long B2[4] = { pk2(b0.x, b0.y), pk2(b0.z, b0.w),
                                         pk2(b1.x, b1.y), pk2(b1.z, b1.w) };
            float aarr[8] = { a0.x, a0.y, a0.z, a0.w, a1.x, a1.y, a1.z, a1.w };
#pragma unroll
            for (int i = 0; i < 8; i++) {
                unsigned long long a2 = pk2(aarr[i], aarr[i]);
#pragma unroll
                for (int j = 0; j < 4; j++) acc[i][j] = ffma2(a2, B2[j], acc[i][j]);
            }
        }
        __syncthreads();
    }

    const int ng0 = nloc0 + tx * 8;
    float bias[8];
#pragma unroll
    for (int j = 0; j < 8; j++) bias[j] = bp[ng0 + j];

    float* out = g_G + (size_t)(m0 + ty * 8) * GFOUR + g * HID + ng0;
#pragma unroll
    for (int i = 0; i < 8; i++) {
        float r[8];
#pragma unroll
        for (int j = 0; j < 4; j++) upk2(acc[i][j], r[2 * j], r[2 * j + 1]);
        float4 v0 = { r[0] + bias[0], r[1] + bias[1], r[2] + bias[2], r[3] + bias[3] };
        float4 v1 = { r[4] + bias[4], r[5] + bias[5], r[6] + bias[6], r[7] + bias[7] };
        *(float4*)(out + (size_t)i * GFOUR)     = v0;
        *(float4*)(out + (size_t)i * GFOUR + 4) = v1;
    }
}

// =====================================================================
// Prep GEMM: U[g][h][hh] = sum_p tgy[g][h][p] * wym[p][hh]
// =====================================================================
__global__ __launch_bounds__(256) void k_gemm_u(
    const float* __restrict__ tf, const float* __restrict__ ti,
    const float* __restrict__ to_, const float* __restrict__ tc,
    const float* __restrict__ wym)
{
    __shared__ float As[8][132];
    __shared__ float Bs[8][132];

    const int g = blockIdx.z;
    const float* ap = (g == 0) ? tf : (g == 1) ? ti : (g == 2) ? to_ : tc;

    const int n0 = blockIdx.x * 128;
    const int m0 = blockIdx.y * 128;

    const int tid  = threadIdx.x;
    const int lrow = tid >> 1;
    const int kq   = (tid & 1) * 4;
    const int kr   = tid >> 5;
    const int nc4  = tid & 31;
    const int tx   = tid & 15;
    const int ty   = tid >> 4;

    unsigned long long acc[8][4];
#pragma unroll
    for (int i = 0; i < 8; i++)
#pragma unroll
        for (int j = 0; j < 4; j++) acc[i][j] = 0ULL;

    const float* Aptr = ap + (size_t)(m0 + lrow) * PROJ + kq;

    for (int k0 = 0; k0 < PROJ; k0 += 8) {
        float4 av = *(const float4*)(Aptr + k0);
        float4 bv = *(const float4*)(wym + (size_t)(k0 + kr) * HID + n0 + nc4 * 4);
        As[kq + 0][lrow] = av.x; As[kq + 1][lrow] = av.y;
        As[kq + 2][lrow] = av.z; As[kq + 3][lrow] = av.w;
        *(float4*)&Bs[kr][nc4 * 4] = bv;
        __syncthreads();
#pragma unroll
        for (int kk = 0; kk < 8; kk++) {
            float4 a0 = *(const float4*)&As[kk][ty * 8];
            float4 a1 = *(const float4*)&As[kk][ty * 8 + 4];
            float4 b0 = *(const float4*)&Bs[kk][tx * 8];
            float4 b1 = *(const float4*)&Bs[kk][tx * 8 + 4];
            unsigned long long B2[4] = { pk2(b0.x, b0.y), pk2(b0.z, b0.w),
                                         pk2(b1.x, b1.y), pk2(b1.z, b1.w) };
            float aarr[8] = { a0.x, a0.y, a0.z, a0.w, a1.x, a1.y, a1.z, a1.w };
#pragma unroll
            for (int i = 0; i < 8; i++) {
                unsigned long long a2 = pk2(aarr[i], aarr[i]);
#pragma unroll
                for (int j = 0; j < 4; j++) acc[i][j] = ffma2(a2, B2[j], acc[i][j]);
            }
        }
        __syncthreads();
    }

    float* out = g_U + (size_t)g * HID * HID + (size_t)(m0 + ty * 8) * HID + n0 + tx * 8;
#pragma unroll
    for (int i = 0; i < 8; i++) {
        float r[8];
#pragma unroll
        for (int j = 0; j < 4; j++) upk2(acc[i][j], r[2 * j], r[2 * j + 1]);
        float4 v0 = { r[0], r[1], r[2], r[3] };
        float4 v1 = { r[4], r[5], r[6], r[7] };
        *(float4*)(out + (size_t)i * HID)     = v0;
        *(float4*)(out + (size_t)i * HID + 4) = v1;
    }
}

// =====================================================================
// Persistent scan: 128 CTAs x 512 threads.
// Partial-dependency barrier: warp w polls ONLY flags of CTAs 8w..8w+7
// (the producers of h columns [64w, 64w+64)), then stages exactly that
// 4KB slice. One hop, no atomics, skew overlaps with staging.
// Dot core identical to R9 (4 pairs x k-half per warp, 2-b unroll,
// dual 6-shfl reduce-scatter trees).
// =====================================================================
__global__ __launch_bounds__(512, 1) void k_scan(float* __restrict__ hout)
{
    extern __shared__ float sm[];
    float* hs   = sm;               // 16*1024 staged h_{t-1}
    float* dots = sm + 16 * 1024;   // [2 kh][32 pairs][17] padded

    const int tid  = threadIdx.x;
    const int lane = tid & 31;
    const int w    = tid >> 5;      // 0..15
    const int wq   = w & 7;
    const int kh   = w >> 3;        // 0,1 k-half
    const int row0 = blockIdx.x * 8;

    // ---- register-resident U slice (half-k per warp) ----
    ulonglong2 wv[4][4];
#pragma unroll
    for (int pp = 0; pp < 4; pp++) {
        const int p = wq * 4 + pp;
        const int g = p >> 3, r = p & 7;
        const ulonglong2* up =
            (const ulonglong2*)(g_U + ((size_t)g * HID + row0 + r) * HID);
#pragma unroll
        for (int j = 0; j < 4; j++) wv[pp][j] = up[kh * 128 + lane + 32 * j];
    }

    // gate-math identity (tid<128): coalesced mapping
    const int r2 = tid & 7;
    const int b2 = (tid >> 3) & 15;
    float creg = 0.0f;

    const bool lowh = lane < 16;
    const unsigned lane8 = lane & 8;

    // staging identity: warp w stages h columns [64w, 64w+64) for all b
    const unsigned* myflag = &g_flags[w * 8 + (lane & 7)];
    const int c16 = lane & 15;      // float4-column within warp's 16
    const int rh  = lane >> 4;      // row half (0/1)

    for (int t = 0; t < T_STEPS; t++) {
        // -------- prefetch input-gate preacts (hidden under dots) ----
        float gf = 0.f, gi = 0.f, go = 0.f, gc = 0.f;
        if (tid < 128) {
            const float* gp = g_G + (size_t)(t * 16 + b2) * GFOUR + row0 + r2;
            gf = __ldg(gp);
            gi = __ldg(gp + HID);
            go = __ldg(gp + 2 * HID);
            gc = __ldg(gp + 3 * HID);
        }

        if (t > 0) {
            // -------- partial barrier: wait for MY 8 producer CTAs --------
            {
                unsigned v;
                bool ok;
                do {
                    asm volatile("ld.acquire.gpu.u32 %0, [%1];"
                                 : "=r"(v) : "l"(myflag) : "memory");
                    ok = __all_sync(0xffffffffu, v >= (unsigned)t);
                } while (!ok);
            }

            // -------- stage my 64-column slice of h_{t-1} --------
            {
                const float4* hp = (const float4*)(hout + (size_t)(t - 1) * (BATCH * HID));
                float4* hs4 = (float4*)hs;
#pragma unroll
                for (int i = 0; i < 8; i++) {
                    const int b = i * 2 + rh;
                    const int idx = b * 256 + w * 16 + c16;
                    hs4[idx] = __ldcg(hp + idx);
                }
            }
            __syncthreads();

            // -------- recurrent dots, 2 batches per iteration --------
            const ulonglong2* hb = (const ulonglong2*)hs;
#pragma unroll 1
            for (int b = 0; b < 16; b += 2) {
                // ---- batch b (A) ----
                unsigned long long a0 = 0ULL, a1 = 0ULL, a2 = 0ULL, a3 = 0ULL;
                {
                    ulonglong2 hf[4];
#pragma unroll
                    for (int j = 0; j < 4; j++)
                        hf[j] = hb[b * 256 + kh * 128 + lane + 32 * j];
#pragma unroll
                    for (int j = 0; j < 4; j++) {
                        a0 = ffma2(hf[j].x, wv[0][j].x, a0);
                        a1 = ffma2(hf[j].x, wv[1][j].x, a1);
                        a2 = ffma2(hf[j].x, wv[2][j].x, a2);
                        a3 = ffma2(hf[j].x, wv[3][j].x, a3);
                        a0 = ffma2(hf[j].y, wv[0][j].y, a0);
                        a1 = ffma2(hf[j].y, wv[1][j].y, a1);
                        a2 = ffma2(hf[j].y, wv[2][j].y, a2);
                        a3 = ffma2(hf[j].y, wv[3][j].y, a3);
                    }
                }
                // ---- batch b+1 (B) ----
                unsigned long long c0 = 0ULL, c1 = 0ULL, c2 = 0ULL, c3 = 0ULL;
                {
                    ulonglong2 hf[4];
#pragma unroll
                    for (int j = 0; j < 4; j++)
                        hf[j] = hb[(b + 1) * 256 + kh * 128 + lane + 32 * j];
#pragma unroll
                    for (int j = 0; j < 4; j++) {
                        c0 = ffma2(hf[j].x, wv[0][j].x, c0);
                        c1 = ffma2(hf[j].x, wv[1][j].x, c1);
                        c2 = ffma2(hf[j].x, wv[2][j].x, c2);
                        c3 = ffma2(hf[j].x, wv[3][j].x, c3);
                        c0 = ffma2(hf[j].y, wv[0][j].y, c0);
                        c1 = ffma2(hf[j].y, wv[1][j].y, c1);
                        c2 = ffma2(hf[j].y, wv[2][j].y, c2);
                        c3 = ffma2(hf[j].y, wv[3][j].y, c3);
                    }
                }

                float lo, hi;
                float fA0, fA1, fA2, fA3, fB0, fB1, fB2, fB3;
                upk2(a0, lo, hi); fA0 = lo + hi;
                upk2(a1, lo, hi); fA1 = lo + hi;
                upk2(a2, lo, hi); fA2 = lo + hi;
                upk2(a3, lo, hi); fA3 = lo + hi;
                upk2(c0, lo, hi); fB0 = lo + hi;
                upk2(c1, lo, hi); fB1 = lo + hi;
                upk2(c2, lo, hi); fB2 = lo + hi;
                upk2(c3, lo, hi); fB3 = lo + hi;

                // ---- two independent 6-shfl reduce-scatter trees ----
                float xA1 = lowh ? fA2 : fA0;
                float xB1 = lowh ? fB2 : fB0;
                float sA0 = (lowh ? fA0 : fA2) + __shfl_xor_sync(0xffffffffu, xA1, 16);
                float sB0 = (lowh ? fB0 : fB2) + __shfl_xor_sync(0xffffffffu, xB1, 16);
                float xA2 = lowh ? fA3 : fA1;
                float xB2 = lowh ? fB3 : fB1;
                float sA1 = (lowh ? fA1 : fA3) + __shfl_xor_sync(0xffffffffu, xA2, 16);
                float sB1 = (lowh ? fB1 : fB3) + __shfl_xor_sync(0xffffffffu, xB2, 16);
                float xA3 = lane8 ? sA0 : sA1;
                float xB3 = lane8 ? sB0 : sB1;
                float sA  = (lane8 ? sA1 : sA0) + __shfl_xor_sync(0xffffffffu, xA3, 8);
                float sB  = (lane8 ? sB1 : sB0) + __shfl_xor_sync(0xffffffffu, xB3, 8);
                sA += __shfl_xor_sync(0xffffffffu, sA, 4);
                sB += __shfl_xor_sync(0xffffffffu, sB, 4);
                sA += __shfl_xor_sync(0xffffffffu, sA, 2);
                sB += __shfl_xor_sync(0xffffffffu, sB, 2);
                sA += __shfl_xor_sync(0xffffffffu, sA, 1);
                sB += __shfl_xor_sync(0xffffffffu, sB, 1);
                // lanes 0/8/16/24 hold sums for pp = 0/1/2/3
                if ((lane & 7) == 0) {
                    const int pidx = (wq * 4 + (lane >> 3)) * 17;
                    dots[kh * 544 + pidx + b]     = sA;
                    dots[kh * 544 + pidx + b + 1] = sB;
                }
            }
        } else {
            for (int i = tid; i < 2 * 32 * 17; i += 512) dots[i] = 0.0f;
        }
        __syncthreads();

        // -------- gate math + cell update + h store --------
        if (tid < 128) {
            const float df = dots[(0 * 8 + r2) * 17 + b2] + dots[544 + (0 * 8 + r2) * 17 + b2];
            const float di = dots[(1 * 8 + r2) * 17 + b2] + dots[544 + (1 * 8 + r2) * 17 + b2];
            const float dg = dots[(2 * 8 + r2) * 17 + b2] + dots[544 + (2 * 8 + r2) * 17 + b2];
            const float dc = dots[(3 * 8 + r2) * 17 + b2] + dots[544 + (3 * 8 + r2) * 17 + b2];
            const float iv = fsig(gi + di);
            const float fv = fsig(gf + df);
            const float ov = fsig(go + dg);
            const float cc = ftanh(gc + dc);
            creg = iv * cc + fv * creg;
            const float hv = ov * tanhf(creg);
            __stcg(hout + (size_t)t * (BATCH * HID) + b2 * HID + row0 + r2, hv);
        }
        __syncthreads();

        // -------- arrive: release own packed flag --------
        if (tid == 0) {
            asm volatile("st.release.gpu.u32 [%0], %1;"
                         :: "l"(&g_flags[blockIdx.x]), "r"((unsigned)(t + 1))
                         : "memory");
        }
    }
}

// =====================================================================
extern "C" void kernel_launch(void* const* d_in, const int* in_sizes, int n_in,
                              void* d_out, int out_size)
{
    const float* x    = (const float*)d_in[0];
    const float* wfxw = (const float*)d_in[1];
    const float* wfxb = (const float*)d_in[2];
    const float* wixw = (const float*)d_in[3];
    const float* wixb = (const float*)d_in[4];
    const float* woxw = (const float*)d_in[5];
    const float* woxb = (const float*)d_in[6];
    const float* wcxw = (const float*)d_in[7];
    const float* wcxb = (const float*)d_in[8];
    const float* tfyw = (const float*)d_in[9];
    const float* tiyw = (const float*)d_in[10];
    const float* toyw = (const float*)d_in[11];
    const float* tcyw = (const float*)d_in[12];
    const float* wymw = (const float*)d_in[13];
    float* out = (float*)d_out;

    (void)in_sizes; (void)n_in; (void)out_size;

    const int scan_smem = (16 * 1024 + 2 * 32 * 17) * (int)sizeof(float);
    cudaFuncSetAttribute(k_scan, cudaFuncAttributeMaxDynamicSharedMemorySize, scan_smem);

    k_init<<<1, 256>>>();
    k_gemm_u<<<dim3(8, 8, 4), 256>>>(tfyw, tiyw, toyw, tcyw, wymw);
    k_gemm_in<<<dim3(32, 125), 256>>>(x, wfxw, wfxb, wixw, wixb,
                                      woxw, woxb, wcxw, wcxb);
    k_scan<<<NCTA, 512, scan_smem>>>(out);
}

// round 17
// speedup vs baseline: 2.1586x; 2.1586x over previous
#include <cuda_runtime.h>
#include <cstdint>
#include <cstdio>

#define T_STEPS 1000
#define BATCH   16
#define IFEAT   440
#define HID     1024
#define PROJ    512
#define NCTA    128
#define GFOUR   4096   // 4*HID

// ---------------- scratch ----------------
__device__ float    g_G[(size_t)T_STEPS * BATCH * GFOUR]; // [t*16+b][g*1024+h]
__device__ float    g_U[(size_t)4 * HID * HID];           // [g][h][hh]
__device__ unsigned g_cnt;

// ---------------- f32x2 helpers ----------------
__device__ __forceinline__ unsigned long long pk2(float x, float y) {
    unsigned long long r;
    asm("mov.b64 %0, {%1, %2};" : "=l"(r) : "f"(x), "f"(y));
    return r;
}
__device__ __forceinline__ void upk2(unsigned long long v, float& x, float& y) {
    asm("mov.b64 {%0, %1}, %2;" : "=f"(x), "=f"(y) : "l"(v));
}
__device__ __forceinline__ unsigned long long ffma2(unsigned long long a,
                                                    unsigned long long b,
                                                    unsigned long long c) {
    unsigned long long d;
    asm("fma.rn.f32x2 %0, %1, %2, %3;" : "=l"(d) : "l"(a), "l"(b), "l"(c));
    return d;
}

// fast sigmoid / tanh (MUFU-based)
__device__ __forceinline__ float fsig(float x) {
    return __fdividef(1.0f, 1.0f + __expf(-x));
}
__device__ __forceinline__ float ftanh(float x) {
    return 1.0f - __fdividef(2.0f, __expf(2.0f * x) + 1.0f);
}

// ---------------- init ----------------
__global__ void k_init() { g_cnt = 0u; }

// =====================================================================
// Input GEMM: G[m][g*1024+n] = x[m][:] . w_g[n][:] + b_g[n]
// =====================================================================
__global__ __launch_bounds__(256) void k_gemm_in(
    const float* __restrict__ x,
    const float* __restrict__ wf, const float* __restrict__ bf,
    const float* __restrict__ wi, const float* __restrict__ bi,
    const float* __restrict__ wo, const float* __restrict__ bo,
    const float* __restrict__ wc, const float* __restrict__ bc)
{
    __shared__ float As[8][132];
    __shared__ float Bs[8][132];

    const int bx = blockIdx.x;            // 0..31 (n tile)
    const int by = blockIdx.y;            // 0..124 (m tile)
    const int g  = bx >> 3;
    const int nloc0 = (bx & 7) * 128;
    const float* wp = (g == 0) ? wf : (g == 1) ? wi : (g == 2) ? wo : wc;
    const float* bp = (g == 0) ? bf : (g == 1) ? bi : (g == 2) ? bo : bc;

    const int tid  = threadIdx.x;
    const int lrow = tid >> 1;
    const int kq   = (tid & 1) * 4;
    const int tx   = tid & 15;
    const int ty   = tid >> 4;

    unsigned long long acc[8][4];
#pragma unroll
    for (int i = 0; i < 8; i++)
#pragma unroll
        for (int j = 0; j < 4; j++) acc[i][j] = 0ULL;

    const int m0 = by * 128;
    const float* Aptr = x  + (size_t)(m0 + lrow)    * IFEAT + kq;
    const float* Bptr = wp + (size_t)(nloc0 + lrow) * IFEAT + kq;

    for (int k0 = 0; k0 < IFEAT; k0 += 8) {
        float4 av = *(const float4*)(Aptr + k0);
        float4 bv = *(const float4*)(Bptr + k0);
        As[kq + 0][lrow] = av.x; As[kq + 1][lrow] = av.y;
        As[kq + 2][lrow] = av.z; As[kq + 3][lrow] = av.w;
        Bs[kq + 0][lrow] = bv.x; Bs[kq + 1][lrow] = bv.y;
        Bs[kq + 2][lrow] = bv.z; Bs[kq + 3][lrow] = bv.w;
        __syncthreads();
#pragma unroll
        for (int kk = 0; kk < 8; kk++) {
            float4 a0 = *(const float4*)&As[kk][ty * 8];
            float4 a1 = *(const float4*)&As[kk][ty * 8 + 4];
            float4 b0 = *(const float4*)&Bs[kk][tx * 8];
            float4 b1 = *(const float4*)&Bs[kk][tx * 8 + 4];
            unsigned long long B2[4] = { pk2(b0.x, b0.y), pk2(b0.z, b0.w),
                                         pk2(b1.x, b1.y), pk2(b1.z, b1.w) };
            float aarr[8] = { a0.x, a0.y, a0.z, a0.w, a1.x, a1.y, a1.z, a1.w };
#pragma unroll
            for (int i = 0; i < 8; i++) {
                unsigned long long a2 = pk2(aarr[i], aarr[i]);
#pragma unroll
                for (int j = 0; j < 4; j++) acc[i][j] = ffma2(a2, B2[j], acc[i][j]);
            }
        }
        __syncthreads();
    }

    const int ng0 = nloc0 + tx * 8;
    float bias[8];
#pragma unroll
    for (int j = 0; j < 8; j++) bias[j] = bp[ng0 + j];

    float* out = g_G + (size_t)(m0 + ty * 8) * GFOUR + g * HID + ng0;
#pragma unroll
    for (int i = 0; i < 8; i++) {
        float r[8];
#pragma unroll
        for (int j = 0; j < 4; j++) upk2(acc[i][j], r[2 * j], r[2 * j + 1]);
        float4 v0 = { r[0] + bias[0], r[1] + bias[1], r[2] + bias[2], r[3] + bias[3] };
        float4 v1 = { r[4] + bias[4], r[5] + bias[5], r[6] + bias[6], r[7] + bias[7] };
        *(float4*)(out + (size_t)i * GFOUR)     = v0;
        *(float4*)(out + (size_t)i * GFOUR + 4) = v1;
    }
}

// =====================================================================
// Prep GEMM: U[g][h][hh] = sum_p tgy[g][h][p] * wym[p][hh]
// =====================================================================
__global__ __launch_bounds__(256) void k_gemm_u(
    const float* __restrict__ tf, const float* __restrict__ ti,
    const float* __restrict__ to_, const float* __restrict__ tc,
    const float* __restrict__ wym)
{
    __shared__ float As[8][132];
    __shared__ float Bs[8][132];

    const int g = blockIdx.z;
    const float* ap = (g == 0) ? tf : (g == 1) ? ti : (g == 2) ? to_ : tc;

    const int n0 = blockIdx.x * 128;
    const int m0 = blockIdx.y * 128;

    const int tid  = threadIdx.x;
    const int lrow = tid >> 1;
    const int kq   = (tid & 1) * 4;
    const int kr   = tid >> 5;
    const int nc4  = tid & 31;
    const int tx   = tid & 15;
    const int ty   = tid >> 4;

    unsigned long long acc[8][4];
#pragma unroll
    for (int i = 0; i < 8; i++)
#pragma unroll
        for (int j = 0; j < 4; j++) acc[i][j] = 0ULL;

    const float* Aptr = ap + (size_t)(m0 + lrow) * PROJ + kq;

    for (int k0 = 0; k0 < PROJ; k0 += 8) {
        float4 av = *(const float4*)(Aptr + k0);
        float4 bv = *(const float4*)(wym + (size_t)(k0 + kr) * HID + n0 + nc4 * 4);
        As[kq + 0][lrow] = av.x; As[kq + 1][lrow] = av.y;
        As[kq + 2][lrow] = av.z; As[kq + 3][lrow] = av.w;
        *(float4*)&Bs[kr][nc4 * 4] = bv;
        __syncthreads();
#pragma unroll
        for (int kk = 0; kk < 8; kk++) {
            float4 a0 = *(const float4*)&As[kk][ty * 8];
            float4 a1 = *(const float4*)&As[kk][ty * 8 + 4];
            float4 b0 = *(const float4*)&Bs[kk][tx * 8];
            float4 b1 = *(const float4*)&Bs[kk][tx * 8 + 4];
            unsigned long long B2[4] = { pk2(b0.x, b0.y), pk2(b0.z, b0.w),
                                         pk2(b1.x, b1.y), pk2(b1.z, b1.w) };
            float aarr[8] = { a0.x, a0.y, a0.z, a0.w, a1.x, a1.y, a1.z, a1.w };
#pragma unroll
            for (int i = 0; i < 8; i++) {
                unsigned long long a2 = pk2(aarr[i], aarr[i]);
#pragma unroll
                for (int j = 0; j < 4; j++) acc[i][j] = ffma2(a2, B2[j], acc[i][j]);
            }
        }
        __syncthreads();
    }

    float* out = g_U + (size_t)g * HID * HID + (size_t)(m0 + ty * 8) * HID + n0 + tx * 8;
#pragma unroll
    for (int i = 0; i < 8; i++) {
        float r[8];
#pragma unroll
        for (int j = 0; j < 4; j++) upk2(acc[i][j], r[2 * j], r[2 * j + 1]);
        float4 v0 = { r[0], r[1], r[2], r[3] };
        float4 v1 = { r[4], r[5], r[6], r[7] };
        *(float4*)(out + (size_t)i * HID)     = v0;
        *(float4*)(out + (size_t)i * HID + 4) = v1;
    }
}

// =====================================================================
// Persistent scan: 128 CTAs x 512 threads, one grid barrier per step.
// (R9 topology — proven best: atomic-add-release arrive, single-thread
// acquire poll, full-CTA staging, 4-pair x k-half warps, 2-b unroll,
// dual 6-shfl reduce-scatter trees.)
// Micro-opts: MUFU gate math, dots stride 17, coalesced gate identity.
// =====================================================================
__global__ __launch_bounds__(512, 1) void k_scan(float* __restrict__ hout)
{
    extern __shared__ float sm[];
    float* hs   = sm;               // 16*1024 staged h_{t-1}
    float* dots = sm + 16 * 1024;   // [2 kh][32 pairs][17] padded

    const int tid  = threadIdx.x;
    const int lane = tid & 31;
    const int w    = tid >> 5;      // 0..15
    const int wq   = w & 7;
    const int kh   = w >> 3;        // 0,1 k-half
    const int row0 = blockIdx.x * 8;

    // ---- register-resident U slice (half-k per warp) ----
    ulonglong2 wv[4][4];
#pragma unroll
    for (int pp = 0; pp < 4; pp++) {
        const int p = wq * 4 + pp;
        const int g = p >> 3, r = p & 7;
        const ulonglong2* up =
            (const ulonglong2*)(g_U + ((size_t)g * HID + row0 + r) * HID);
#pragma unroll
        for (int j = 0; j < 4; j++) wv[pp][j] = up[kh * 128 + lane + 32 * j];
    }

    // gate-math identity (tid<128): coalesced mapping (8 consecutive h rows
    // per lane octet -> 4 sectors/warp for both G loads and h stores)
    const int r2 = tid & 7;
    const int b2 = (tid >> 3) & 15;
    float creg = 0.0f;

    const bool lowh = lane < 16;
    const unsigned lane8 = lane & 8;

    for (int t = 0; t < T_STEPS; t++) {
        // -------- prefetch input-gate preacts (hidden under barrier+dots) ----
        float gf = 0.f, gi = 0.f, go = 0.f, gc = 0.f;
        if (tid < 128) {
            const float* gp = g_G + (size_t)(t * 16 + b2) * GFOUR + row0 + r2;
            gf = __ldg(gp);
            gi = __ldg(gp + HID);
            go = __ldg(gp + 2 * HID);
            gc = __ldg(gp + 3 * HID);
        }

        if (t > 0) {
            // -------- grid barrier: wait until all CTAs finished step t-1 ----
            if (tid == 0) {
                unsigned v;
                do {
                    asm volatile("ld.acquire.gpu.u32 %0, [%1];"
                                 : "=r"(v) : "l"(&g_cnt) : "memory");
                } while (v < (unsigned)(NCTA * t));
            }
            __syncthreads();

            // -------- stage h_{t-1} into smem (from L2) --------
            {
                const float4* hp = (const float4*)(hout + (size_t)(t - 1) * (BATCH * HID));
                float4* hs4 = (float4*)hs;
#pragma unroll
                for (int i = 0; i < 8; i++)
                    hs4[tid + i * 512] = __ldcg(hp + tid + i * 512);
            }
            __syncthreads();

            // -------- recurrent dots, 2 batches per iteration --------
            const ulonglong2* hb = (const ulonglong2*)hs;
#pragma unroll 1
            for (int b = 0; b < 16; b += 2) {
                // ---- batch b (A) ----
                unsigned long long a0 = 0ULL, a1 = 0ULL, a2 = 0ULL, a3 = 0ULL;
                {
                    ulonglong2 hf[4];
#pragma unroll
                    for (int j = 0; j < 4; j++)
                        hf[j] = hb[b * 256 + kh * 128 + lane + 32 * j];
#pragma unroll
                    for (int j = 0; j < 4; j++) {
                        a0 = ffma2(hf[j].x, wv[0][j].x, a0);
                        a1 = ffma2(hf[j].x, wv[1][j].x, a1);
                        a2 = ffma2(hf[j].x, wv[2][j].x, a2);
                        a3 = ffma2(hf[j].x, wv[3][j].x, a3);
                        a0 = ffma2(hf[j].y, wv[0][j].y, a0);
                        a1 = ffma2(hf[j].y, wv[1][j].y, a1);
                        a2 = ffma2(hf[j].y, wv[2][j].y, a2);
                        a3 = ffma2(hf[j].y, wv[3][j].y, a3);
                    }
                }
                // ---- batch b+1 (B) ----
                unsigned long long c0 = 0ULL, c1 = 0ULL, c2 = 0ULL, c3 = 0ULL;
                {
                    ulonglong2 hf[4];
#pragma unroll
                    for (int j = 0; j < 4; j++)
                        hf[j] = hb[(b + 1) * 256 + kh * 128 + lane + 32 * j];
#pragma unroll
                    for (int j = 0; j < 4; j++) {
                        c0 = ffma2(hf[j].x, wv[0][j].x, c0);
                        c1 = ffma2(hf[j].x, wv[1][j].x, c1);
                        c2 = ffma2(hf[j].x, wv[2][j].x, c2);
                        c3 = ffma2(hf[j].x, wv[3][j].x, c3);
                        c0 = ffma2(hf[j].y, wv[0][j].y, c0);
                        c1 = ffma2(hf[j].y, wv[1][j].y, c1);
                        c2 = ffma2(hf[j].y, wv[2][j].y, c2);
                        c3 = ffma2(hf[j].y, wv[3][j].y, c3);
                    }
                }

                float lo, hi;
                float fA0, fA1, fA2, fA3, fB0, fB1, fB2, fB3;
                upk2(a0, lo, hi); fA0 = lo + hi;
                upk2(a1, lo, hi); fA1 = lo + hi;
                upk2(a2, lo, hi); fA2 = lo + hi;
                upk2(a3, lo, hi); fA3 = lo + hi;
                upk2(c0, lo, hi); fB0 = lo + hi;
                upk2(c1, lo, hi); fB1 = lo + hi;
                upk2(c2, lo, hi); fB2 = lo + hi;
                upk2(c3, lo, hi); fB3 = lo + hi;

                // ---- two independent 6-shfl reduce-scatter trees ----
                float xA1 = lowh ? fA2 : fA0;
                float xB1 = lowh ? fB2 : fB0;
                float sA0 = (lowh ? fA0 : fA2) + __shfl_xor_sync(0xffffffffu, xA1, 16);
                float sB0 = (lowh ? fB0 : fB2) + __shfl_xor_sync(0xffffffffu, xB1, 16);
                float xA2 = lowh ? fA3 : fA1;
                float xB2 = lowh ? fB3 : fB1;
                float sA1 = (lowh ? fA1 : fA3) + __shfl_xor_sync(0xffffffffu, xA2, 16);
                float sB1 = (lowh ? fB1 : fB3) + __shfl_xor_sync(0xffffffffu, xB2, 16);
                float xA3 = lane8 ? sA0 : sA1;
                float xB3 = lane8 ? sB0 : sB1;
                float sA  = (lane8 ? sA1 : sA0) + __shfl_xor_sync(0xffffffffu, xA3, 8);
                float sB  = (lane8 ? sB1 : sB0) + __shfl_xor_sync(0xffffffffu, xB3, 8);
                sA += __shfl_xor_sync(0xffffffffu, sA, 4);
                sB += __shfl_xor_sync(0xffffffffu, sB, 4);
                sA += __shfl_xor_sync(0xffffffffu, sA, 2);
                sB += __shfl_xor_sync(0xffffffffu, sB, 2);
                sA += __shfl_xor_sync(0xffffffffu, sA, 1);
                sB += __shfl_xor_sync(0xffffffffu, sB, 1);
                // lanes 0/8/16/24 hold sums for pp = 0/1/2/3
                if ((lane & 7) == 0) {
                    const int pidx = (wq * 4 + (lane >> 3)) * 17;
                    dots[kh * 544 + pidx + b]     = sA;
                    dots[kh * 544 + pidx + b + 1] = sB;
                }
            }
        } else {
            for (int i = tid; i < 2 * 32 * 17; i += 512) dots[i] = 0.0f;
        }
        __syncthreads();

        // -------- gate math + cell update + h store --------
        if (tid < 128) {
            const float df = dots[(0 * 8 + r2) * 17 + b2] + dots[544 + (0 * 8 + r2) * 17 + b2];
            const float di = dots[(1 * 8 + r2) * 17 + b2] + dots[544 + (1 * 8 + r2) * 17 + b2];
            const float dg = dots[(2 * 8 + r2) * 17 + b2] + dots[544 + (2 * 8 + r2) * 17 + b2];
            const float dc = dots[(3 * 8 + r2) * 17 + b2] + dots[544 + (3 * 8 + r2) * 17 + b2];
            const float iv = fsig(gi + di);
            const float fv = fsig(gf + df);
            const float ov = fsig(go + dg);
            const float cc = ftanh(gc + dc);
            creg = iv * cc + fv * creg;
            const float hv = ov * ftanh(creg);
            __stcg(hout + (size_t)t * (BATCH * HID) + b2 * HID + row0 + r2, hv);
        }
        __syncthreads();

        // -------- arrive (release orders the h stores after syncthreads) ----
        if (tid == 0) {
            unsigned old;
            asm volatile("atom.add.release.gpu.u32 %0, [%1], %2;"
                         : "=r"(old) : "l"(&g_cnt), "r"(1u) : "memory");
        }
    }
}

// =====================================================================
extern "C" void kernel_launch(void* const* d_in, const int* in_sizes, int n_in,
                              void* d_out, int out_size)
{
    const float* x    = (const float*)d_in[0];
    const float* wfxw = (const float*)d_in[1];
    const float* wfxb = (const float*)d_in[2];
    const float* wixw = (const float*)d_in[3];
    const float* wixb = (const float*)d_in[4];
    const float* woxw = (const float*)d_in[5];
    const float* woxb = (const float*)d_in[6];
    const float* wcxw = (const float*)d_in[7];
    const float* wcxb = (const float*)d_in[8];
    const float* tfyw = (const float*)d_in[9];
    const float* tiyw = (const float*)d_in[10];
    const float* toyw = (const float*)d_in[11];
    const float* tcyw = (const float*)d_in[12];
    const float* wymw = (const float*)d_in[13];
    float* out = (float*)d_out;

    (void)in_sizes; (void)n_in; (void)out_size;

    const int scan_smem = (16 * 1024 + 2 * 32 * 17) * (int)sizeof(float);
    cudaFuncSetAttribute(k_scan, cudaFuncAttributeMaxDynamicSharedMemorySize, scan_smem);

    k_init<<<1, 1>>>();
    k_gemm_u<<<dim3(8, 8, 4), 256>>>(tfyw, tiyw, toyw, tcyw, wymw);
    k_gemm_in<<<dim3(32, 125), 256>>>(x, wfxw, wfxb, wixw, wixb,
                                      woxw, woxb, wcxw, wcxb);
    k_scan<<<NCTA, 512, scan_smem>>>(out);
}